// round 1
// baseline (speedup 1.0000x reference)
#include <cuda_runtime.h>

// ---------------------------------------------------------------------------
// Packed f32x2 helpers (Blackwell FFMA2 via PTX fma.rn.f32x2)
// ---------------------------------------------------------------------------
__device__ __forceinline__ unsigned long long pack2(float a, float b) {
    unsigned long long r;
    asm("mov.b64 %0, {%1, %2};" : "=l"(r) : "f"(a), "f"(b));
    return r;
}
__device__ __forceinline__ void unpack2(unsigned long long v, float& a, float& b) {
    asm("mov.b64 {%0, %1}, %2;" : "=f"(a), "=f"(b) : "l"(v));
}
__device__ __forceinline__ void ffma2(unsigned long long& d,
                                      unsigned long long a,
                                      unsigned long long b) {
    asm("fma.rn.f32x2 %0, %1, %2, %0;" : "+l"(d) : "l"(a), "l"(b));
}

// ---------------------------------------------------------------------------
// Scratch (device globals; allocation-free)
// ---------------------------------------------------------------------------
__device__ float g_w1 [ 2097152];  // [8,   4,256,256]
__device__ float g_cat2[16777216]; // [8,  32,256,256]  c1 @0..15, iwt(ic2) @16..31
__device__ float g_w2 [ 8388608];  // [8,  64,128,128]
__device__ float g_cat3[16777216]; // [8, 128,128,128]  c2 @0..63, iwt(ic3) @64..127
__device__ float g_w3 [ 8388608];  // [8, 256, 64, 64]
__device__ float g_cat4[16777216]; // [8, 512, 64, 64]  c3 @0..255, iwt(ic4) @256..511
__device__ float g_w4 [ 8388608];  // [8,1024, 32, 32]
__device__ float g_c4 [ 8388608];
__device__ float g_c5 [ 8388608];
__device__ float g_ic4[ 8388608];
__device__ float g_ic3[ 8388608];  // [8, 256, 64, 64]
__device__ float g_ic2[ 8388608];  // [8,  64,128,128]
__device__ float g_ic1[ 8388608];  // [8,  16,256,256]
__device__ float g_iw1[ 2097152];  // [8,   4,256,256]

// ---------------------------------------------------------------------------
// Haar wavelet forward: in [B,C(view),2Ho,2Wo] -> out [B,4C,Ho,Wo]
// out channel = c*4 + k ; bands 1..3 rescaled (y+1)*0.5
// ---------------------------------------------------------------------------
__global__ void wt_k(const float* __restrict__ in, int inCtot, int inCoff,
                     float* __restrict__ out, int C, int Ho, int Wo, int total) {
    int idx = blockIdx.x * blockDim.x + threadIdx.x;
    if (idx >= total) return;
    int wo = idx % Wo; int t = idx / Wo;
    int ho = t % Ho;  t /= Ho;
    int c  = t % C;   int b = t / C;
    int Wi = 2 * Wo, Hi = 2 * Ho;
    const float* p = in + (((long long)b * inCtot + inCoff + c) * Hi + 2 * ho) * Wi + 2 * wo;
    float x00 = p[0], x01 = p[1], x10 = p[Wi], x11 = p[Wi + 1];
    float y0 = 0.25f * (x00 + x01 + x10 + x11);
    float y1 = 0.5f  * (x00 + x01 - x10 - x11);
    float y2 = 0.5f  * (x00 - x01 + x10 - x11);
    float y3 = 0.5f  * (x00 - x01 - x10 + x11);
    long long s  = (long long)Ho * Wo;
    long long ob = (((long long)b * (4 * C) + c * 4) * Ho + ho) * Wo + wo;
    out[ob]         = y0;
    out[ob + s]     = 0.5f * y1 + 0.5f;
    out[ob + 2 * s] = 0.5f * y2 + 0.5f;
    out[ob + 3 * s] = 0.5f * y3 + 0.5f;
}

// ---------------------------------------------------------------------------
// Haar wavelet inverse: in [B,4C,H,W] (plain) -> out [B,C(view),2H,2W]
// bands 1..3 un-rescaled 2y-1 first; optional fused sigmoid
// ---------------------------------------------------------------------------
__global__ void iwt_k(const float* __restrict__ in, int C, int H, int W,
                      float* __restrict__ out, int outCtot, int outCoff,
                      int doSigmoid, int total) {
    int idx = blockIdx.x * blockDim.x + threadIdx.x;
    if (idx >= total) return;
    int w = idx % W; int t = idx / W;
    int h = t % H;  t /= H;
    int c = t % C;  int b = t / C;
    long long s  = (long long)H * W;
    long long ib = (((long long)b * (4 * C) + 4 * c) * H + h) * W + w;
    float y0 = in[ib];
    float t1 = 2.f * in[ib + s]     - 1.f;
    float t2 = 2.f * in[ib + 2 * s] - 1.f;
    float t3 = 2.f * in[ib + 3 * s] - 1.f;
    float x00 = y0 + 0.5f * ( t1 + t2 + t3);
    float x01 = y0 + 0.5f * ( t1 - t2 - t3);
    float x10 = y0 + 0.5f * (-t1 + t2 - t3);
    float x11 = y0 + 0.5f * (-t1 - t2 + t3);
    if (doSigmoid) {
        x00 = 1.f / (1.f + expf(-x00));
        x01 = 1.f / (1.f + expf(-x01));
        x10 = 1.f / (1.f + expf(-x10));
        x11 = 1.f / (1.f + expf(-x11));
    }
    int W2 = 2 * W;
    float* o = out + (((long long)b * outCtot + outCoff + c) * (2 * H) + 2 * h) * W2 + 2 * w;
    o[0] = x00; o[1] = x01; o[W2] = x10; o[W2 + 1] = x11;
}

// ---------------------------------------------------------------------------
// Direct 3x3 conv (pad 1), 32x32 spatial tile, 256 threads,
// each thread: 4 vertical pixels x (2*PAIRS) output channels (packed f32x2).
// Optional addend (residual) and leaky-relu epilogue. Channel-sliced I/O for
// fused concat (ctot/coff).
// ---------------------------------------------------------------------------
template <int PAIRS>
__global__ __launch_bounds__(256)
void conv3x3_k(const float* __restrict__ in, int Cin, int inCtot, int inCoff,
               const float* __restrict__ wgt, const float* __restrict__ bias,
               float* __restrict__ out, int outCtot, int outCoff,
               int H, int W, int numCog,
               const float* __restrict__ addend, int addCtot, int addCoff,
               int doLrelu) {
    __shared__ float patch[34 * 34];
    __shared__ unsigned long long wsm[PAIRS * 9];

    const int tx  = threadIdx.x;            // 0..31
    const int ty  = threadIdx.y;            // 0..7
    const int tid = ty * 32 + tx;
    const int b   = blockIdx.z / numCog;
    const int cog = blockIdx.z % numCog;
    const int ox  = blockIdx.x * 32 + tx;
    const int oy0 = blockIdx.y * 32 + ty * 4;
    const int co0 = cog * (2 * PAIRS);
    const int gx0 = blockIdx.x * 32 - 1;
    const int gy0 = blockIdx.y * 32 - 1;

    unsigned long long acc[PAIRS][4];
#pragma unroll
    for (int pr = 0; pr < PAIRS; pr++)
#pragma unroll
        for (int p = 0; p < 4; p++) acc[pr][p] = 0ULL;

    for (int ci = 0; ci < Cin; ci++) {
        __syncthreads();
        const float* inc = in + ((long long)b * inCtot + inCoff + ci) * H * W;
        for (int idx = tid; idx < 34 * 34; idx += 256) {
            int py = idx / 34, px = idx % 34;
            int gy = gy0 + py, gx = gx0 + px;
            float v = 0.f;
            if (gy >= 0 && gy < H && gx >= 0 && gx < W) v = inc[gy * W + gx];
            patch[idx] = v;
        }
        if (tid < PAIRS * 9) {
            int pr = tid / 9, j = tid % 9;
            int c0 = co0 + 2 * pr;
            wsm[tid] = pack2(wgt[((long long)c0 * Cin + ci) * 9 + j],
                             wgt[((long long)(c0 + 1) * Cin + ci) * 9 + j]);
        }
        __syncthreads();

        // 18 input values (6 rows x 3 cols) packed {v,v}
        unsigned long long v2[6][3];
#pragma unroll
        for (int r = 0; r < 6; r++)
#pragma unroll
            for (int d = 0; d < 3; d++) {
                float v = patch[(ty * 4 + r) * 34 + tx + d];
                v2[r][d] = pack2(v, v);
            }

#pragma unroll
        for (int pr = 0; pr < PAIRS; pr++) {
            unsigned long long w2[9];
#pragma unroll
            for (int j = 0; j < 9; j++) w2[j] = wsm[pr * 9 + j];
#pragma unroll
            for (int p = 0; p < 4; p++) {
#pragma unroll
                for (int dy = 0; dy < 3; dy++)
#pragma unroll
                    for (int dx = 0; dx < 3; dx++)
                        ffma2(acc[pr][p], w2[dy * 3 + dx], v2[p + dy][dx]);
            }
        }
    }

    // epilogue
#pragma unroll
    for (int pr = 0; pr < PAIRS; pr++) {
        int c0 = co0 + 2 * pr;
        float b0 = bias[c0], b1 = bias[c0 + 1];
#pragma unroll
        for (int p = 0; p < 4; p++) {
            float r0, r1;
            unpack2(acc[pr][p], r0, r1);
            r0 += b0; r1 += b1;
            int oy = oy0 + p;
            if (addend) {
                r0 += addend[(((long long)b * addCtot + addCoff + c0)     * H + oy) * W + ox];
                r1 += addend[(((long long)b * addCtot + addCoff + c0 + 1) * H + oy) * W + ox];
            }
            if (doLrelu) {
                r0 = r0 > 0.f ? r0 : 0.2f * r0;
                r1 = r1 > 0.f ? r1 : 0.2f * r1;
            }
            out[(((long long)b * outCtot + outCoff + c0)     * H + oy) * W + ox] = r0;
            out[(((long long)b * outCtot + outCoff + c0 + 1) * H + oy) * W + ox] = r1;
        }
    }
}

// ---------------------------------------------------------------------------
// Orchestration
// ---------------------------------------------------------------------------
static inline void launch_conv(const float* in, int Cin, int inCtot, int inCoff,
                               const float* w, const float* bvec,
                               float* out, int Cout, int outCtot, int outCoff,
                               int H, int W,
                               const float* addend, int addCtot, int addCoff,
                               int doLrelu) {
    dim3 bdim(32, 8);
    if (Cout >= 8) {
        int numCog = Cout / 8;
        dim3 grid(W / 32, H / 32, 8 * numCog);
        conv3x3_k<4><<<grid, bdim>>>(in, Cin, inCtot, inCoff, w, bvec,
                                     out, outCtot, outCoff, H, W, numCog,
                                     addend, addCtot, addCoff, doLrelu);
    } else {  // Cout == 4
        int numCog = Cout / 4;
        dim3 grid(W / 32, H / 32, 8 * numCog);
        conv3x3_k<2><<<grid, bdim>>>(in, Cin, inCtot, inCoff, w, bvec,
                                     out, outCtot, outCoff, H, W, numCog,
                                     addend, addCtot, addCoff, doLrelu);
    }
}

extern "C" void kernel_launch(void* const* d_in, const int* in_sizes, int n_in,
                              void* d_out, int out_size) {
    const float* x        = (const float*)d_in[0];
    const float* conv1_w  = (const float*)d_in[1];
    const float* conv1_b  = (const float*)d_in[2];
    const float* conv2_w  = (const float*)d_in[3];
    const float* conv2_b  = (const float*)d_in[4];
    const float* conv3_w  = (const float*)d_in[5];
    const float* conv3_b  = (const float*)d_in[6];
    const float* conv4_w  = (const float*)d_in[7];
    const float* conv4_b  = (const float*)d_in[8];
    const float* convd1_w = (const float*)d_in[9];
    const float* convd1_b = (const float*)d_in[10];
    const float* convd2_w = (const float*)d_in[11];
    const float* convd2_b = (const float*)d_in[12];
    const float* convd3_w = (const float*)d_in[13];
    const float* convd3_b = (const float*)d_in[14];
    const float* convd4_w = (const float*)d_in[15];
    const float* convd4_b = (const float*)d_in[16];
    float* out = (float*)d_out;

    float *w1, *cat2, *w2, *cat3, *w3, *cat4, *w4, *c4, *c5, *ic4, *ic3, *ic2, *ic1, *iw1;
    cudaGetSymbolAddress((void**)&w1,  g_w1);
    cudaGetSymbolAddress((void**)&cat2, g_cat2);
    cudaGetSymbolAddress((void**)&w2,  g_w2);
    cudaGetSymbolAddress((void**)&cat3, g_cat3);
    cudaGetSymbolAddress((void**)&w3,  g_w3);
    cudaGetSymbolAddress((void**)&cat4, g_cat4);
    cudaGetSymbolAddress((void**)&w4,  g_w4);
    cudaGetSymbolAddress((void**)&c4,  g_c4);
    cudaGetSymbolAddress((void**)&c5,  g_c5);
    cudaGetSymbolAddress((void**)&ic4, g_ic4);
    cudaGetSymbolAddress((void**)&ic3, g_ic3);
    cudaGetSymbolAddress((void**)&ic2, g_ic2);
    cudaGetSymbolAddress((void**)&ic1, g_ic1);
    cudaGetSymbolAddress((void**)&iw1, g_iw1);

    const int B = 8;
    int tot;

    // --- encoder ---
    tot = B * 1 * 256 * 256;                                         // wt(x) -> w1 [8,4,256,256]
    wt_k<<<(tot + 255) / 256, 256>>>(x, 1, 0, w1, 1, 256, 256, tot);

    // c1 = lrelu(conv1(w1)) -> cat2[ch 0..15]
    launch_conv(w1, 4, 4, 0, conv1_w, conv1_b, cat2, 16, 32, 0, 256, 256, nullptr, 0, 0, 1);

    tot = B * 16 * 128 * 128;                                        // wt(c1) -> w2
    wt_k<<<(tot + 255) / 256, 256>>>(cat2, 32, 0, w2, 16, 128, 128, tot);

    // c2 = lrelu(conv2(w2)) -> cat3[ch 0..63]
    launch_conv(w2, 64, 64, 0, conv2_w, conv2_b, cat3, 64, 128, 0, 128, 128, nullptr, 0, 0, 1);

    tot = B * 64 * 64 * 64;                                          // wt(c2) -> w3
    wt_k<<<(tot + 255) / 256, 256>>>(cat3, 128, 0, w3, 64, 64, 64, tot);

    // c3 = lrelu(conv3(w3)) -> cat4[ch 0..255]
    launch_conv(w3, 256, 256, 0, conv3_w, conv3_b, cat4, 256, 512, 0, 64, 64, nullptr, 0, 0, 1);

    tot = B * 256 * 32 * 32;                                         // wt(c3) -> w4
    wt_k<<<(tot + 255) / 256, 256>>>(cat4, 512, 0, w4, 256, 32, 32, tot);

    // --- bottleneck: conv4 x3 ---
    launch_conv(w4, 1024, 1024, 0, conv4_w, conv4_b, c4, 1024, 1024, 0, 32, 32, nullptr, 0, 0, 1);
    launch_conv(c4, 1024, 1024, 0, conv4_w, conv4_b, c5, 1024, 1024, 0, 32, 32, nullptr, 0, 0, 1);
    // ic4 = lrelu(conv4(c5) + w4)
    launch_conv(c5, 1024, 1024, 0, conv4_w, conv4_b, ic4, 1024, 1024, 0, 32, 32, w4, 1024, 0, 1);

    // --- decoder ---
    tot = B * 256 * 32 * 32;                                         // iwt(ic4) -> cat4[ch 256..511]
    iwt_k<<<(tot + 255) / 256, 256>>>(ic4, 256, 32, 32, cat4, 512, 256, 0, tot);

    // ic3 = lrelu(convd4(cat4))
    launch_conv(cat4, 512, 512, 0, convd4_w, convd4_b, ic3, 256, 256, 0, 64, 64, nullptr, 0, 0, 1);

    tot = B * 64 * 64 * 64;                                          // iwt(ic3) -> cat3[ch 64..127]
    iwt_k<<<(tot + 255) / 256, 256>>>(ic3, 64, 64, 64, cat3, 128, 64, 0, tot);

    // ic2 = lrelu(convd3(cat3))
    launch_conv(cat3, 128, 128, 0, convd3_w, convd3_b, ic2, 64, 64, 0, 128, 128, nullptr, 0, 0, 1);

    tot = B * 16 * 128 * 128;                                        // iwt(ic2) -> cat2[ch 16..31]
    iwt_k<<<(tot + 255) / 256, 256>>>(ic2, 16, 128, 128, cat2, 32, 16, 0, tot);

    // ic1 = lrelu(convd2(cat2))
    launch_conv(cat2, 32, 32, 0, convd2_w, convd2_b, ic1, 16, 16, 0, 256, 256, nullptr, 0, 0, 1);

    // iw1 = lrelu(convd1(ic1))
    launch_conv(ic1, 16, 16, 0, convd1_w, convd1_b, iw1, 4, 4, 0, 256, 256, nullptr, 0, 0, 1);

    tot = B * 1 * 256 * 256;                                         // sigmoid(iwt(iw1)) -> out
    iwt_k<<<(tot + 255) / 256, 256>>>(iw1, 1, 256, 256, out, 1, 0, 1, tot);

    (void)in_sizes; (void)n_in; (void)out_size;
}

// round 2
// speedup vs baseline: 4.7022x; 4.7022x over previous
#include <cuda_runtime.h>

// ---------------------------------------------------------------------------
// Packed f32x2 helpers (Blackwell FFMA2 via PTX fma.rn.f32x2)
// ---------------------------------------------------------------------------
__device__ __forceinline__ unsigned long long pack2(float a, float b) {
    unsigned long long r;
    asm("mov.b64 %0, {%1, %2};" : "=l"(r) : "f"(a), "f"(b));
    return r;
}
__device__ __forceinline__ void unpack2(unsigned long long v, float& a, float& b) {
    asm("mov.b64 {%0, %1}, %2;" : "=f"(a), "=f"(b) : "l"(v));
}
__device__ __forceinline__ void ffma2(unsigned long long& d,
                                      unsigned long long a,
                                      unsigned long long b) {
    asm("fma.rn.f32x2 %0, %1, %2, %0;" : "+l"(d) : "l"(a), "l"(b));
}

// tf32 round-to-nearest conversion (keeps bits in a .b32 reg)
__device__ __forceinline__ unsigned tf32b(float x) {
    unsigned r;
    asm("cvt.rna.tf32.f32 %0, %1;" : "=r"(r) : "f"(x));
    return r;
}

__device__ __forceinline__ void mma8(float d[4], const unsigned a[4],
                                     unsigned b0, unsigned b1) {
    asm("mma.sync.aligned.m16n8k8.row.col.f32.tf32.tf32.f32 "
        "{%0,%1,%2,%3},{%4,%5,%6,%7},{%8,%9},{%0,%1,%2,%3};"
        : "+f"(d[0]), "+f"(d[1]), "+f"(d[2]), "+f"(d[3])
        : "r"(a[0]), "r"(a[1]), "r"(a[2]), "r"(a[3]), "r"(b0), "r"(b1));
}

// ---------------------------------------------------------------------------
// Scratch (device globals; allocation-free)
// ---------------------------------------------------------------------------
__device__ float g_w1 [ 2097152];  // [8,   4,256,256]
__device__ float g_cat2[16777216]; // [8,  32,256,256]  c1 @0..15, iwt(ic2) @16..31
__device__ float g_w2 [ 8388608];  // [8,  64,128,128]
__device__ float g_cat3[16777216]; // [8, 128,128,128]  c2 @0..63, iwt(ic3) @64..127
__device__ float g_w3 [ 8388608];  // [8, 256, 64, 64]
__device__ float g_cat4[16777216]; // [8, 512, 64, 64]  c3 @0..255, iwt(ic4) @256..511
__device__ float g_w4 [ 8388608];  // [8,1024, 32, 32]
__device__ float g_c4 [ 8388608];
__device__ float g_c5 [ 8388608];
__device__ float g_ic4[ 8388608];
__device__ float g_ic3[ 8388608];  // [8, 256, 64, 64]
__device__ float g_ic2[ 8388608];  // [8,  64,128,128]
__device__ float g_ic1[ 8388608];  // [8,  16,256,256]
__device__ float g_iw1[ 2097152];  // [8,   4,256,256]

// ---------------------------------------------------------------------------
// Haar wavelet forward
// ---------------------------------------------------------------------------
__global__ void wt_k(const float* __restrict__ in, int inCtot, int inCoff,
                     float* __restrict__ out, int C, int Ho, int Wo, int total) {
    int idx = blockIdx.x * blockDim.x + threadIdx.x;
    if (idx >= total) return;
    int wo = idx % Wo; int t = idx / Wo;
    int ho = t % Ho;  t /= Ho;
    int c  = t % C;   int b = t / C;
    int Wi = 2 * Wo, Hi = 2 * Ho;
    const float* p = in + (((long long)b * inCtot + inCoff + c) * Hi + 2 * ho) * Wi + 2 * wo;
    float x00 = p[0], x01 = p[1], x10 = p[Wi], x11 = p[Wi + 1];
    float y0 = 0.25f * (x00 + x01 + x10 + x11);
    float y1 = 0.5f  * (x00 + x01 - x10 - x11);
    float y2 = 0.5f  * (x00 - x01 + x10 - x11);
    float y3 = 0.5f  * (x00 - x01 - x10 + x11);
    long long s  = (long long)Ho * Wo;
    long long ob = (((long long)b * (4 * C) + c * 4) * Ho + ho) * Wo + wo;
    out[ob]         = y0;
    out[ob + s]     = 0.5f * y1 + 0.5f;
    out[ob + 2 * s] = 0.5f * y2 + 0.5f;
    out[ob + 3 * s] = 0.5f * y3 + 0.5f;
}

// ---------------------------------------------------------------------------
// Haar wavelet inverse (optional fused sigmoid)
// ---------------------------------------------------------------------------
__global__ void iwt_k(const float* __restrict__ in, int C, int H, int W,
                      float* __restrict__ out, int outCtot, int outCoff,
                      int doSigmoid, int total) {
    int idx = blockIdx.x * blockDim.x + threadIdx.x;
    if (idx >= total) return;
    int w = idx % W; int t = idx / W;
    int h = t % H;  t /= H;
    int c = t % C;  int b = t / C;
    long long s  = (long long)H * W;
    long long ib = (((long long)b * (4 * C) + 4 * c) * H + h) * W + w;
    float y0 = in[ib];
    float t1 = 2.f * in[ib + s]     - 1.f;
    float t2 = 2.f * in[ib + 2 * s] - 1.f;
    float t3 = 2.f * in[ib + 3 * s] - 1.f;
    float x00 = y0 + 0.5f * ( t1 + t2 + t3);
    float x01 = y0 + 0.5f * ( t1 - t2 - t3);
    float x10 = y0 + 0.5f * (-t1 + t2 - t3);
    float x11 = y0 + 0.5f * (-t1 - t2 + t3);
    if (doSigmoid) {
        x00 = 1.f / (1.f + expf(-x00));
        x01 = 1.f / (1.f + expf(-x01));
        x10 = 1.f / (1.f + expf(-x10));
        x11 = 1.f / (1.f + expf(-x11));
    }
    int W2 = 2 * W;
    float* o = out + (((long long)b * outCtot + outCoff + c) * (2 * H) + 2 * h) * W2 + 2 * w;
    o[0] = x00; o[1] = x01; o[W2] = x10; o[W2 + 1] = x11;
}

// ---------------------------------------------------------------------------
// Scalar FFMA2 direct 3x3 conv — used only for the tiny-channel layers
// ---------------------------------------------------------------------------
template <int PAIRS>
__global__ __launch_bounds__(256)
void conv3x3_k(const float* __restrict__ in, int Cin, int inCtot, int inCoff,
               const float* __restrict__ wgt, const float* __restrict__ bias,
               float* __restrict__ out, int outCtot, int outCoff,
               int H, int W, int numCog,
               const float* __restrict__ addend, int addCtot, int addCoff,
               int doLrelu) {
    __shared__ float patch[34 * 34];
    __shared__ unsigned long long wsm[PAIRS * 9];

    const int tx  = threadIdx.x;
    const int ty  = threadIdx.y;
    const int tid = ty * 32 + tx;
    const int b   = blockIdx.z / numCog;
    const int cog = blockIdx.z % numCog;
    const int ox  = blockIdx.x * 32 + tx;
    const int oy0 = blockIdx.y * 32 + ty * 4;
    const int co0 = cog * (2 * PAIRS);
    const int gx0 = blockIdx.x * 32 - 1;
    const int gy0 = blockIdx.y * 32 - 1;

    unsigned long long acc[PAIRS][4];
#pragma unroll
    for (int pr = 0; pr < PAIRS; pr++)
#pragma unroll
        for (int p = 0; p < 4; p++) acc[pr][p] = 0ULL;

    for (int ci = 0; ci < Cin; ci++) {
        __syncthreads();
        const float* inc = in + ((long long)b * inCtot + inCoff + ci) * H * W;
        for (int idx = tid; idx < 34 * 34; idx += 256) {
            int py = idx / 34, px = idx % 34;
            int gy = gy0 + py, gx = gx0 + px;
            float v = 0.f;
            if (gy >= 0 && gy < H && gx >= 0 && gx < W) v = inc[gy * W + gx];
            patch[idx] = v;
        }
        if (tid < PAIRS * 9) {
            int pr = tid / 9, j = tid % 9;
            int c0 = co0 + 2 * pr;
            wsm[tid] = pack2(wgt[((long long)c0 * Cin + ci) * 9 + j],
                             wgt[((long long)(c0 + 1) * Cin + ci) * 9 + j]);
        }
        __syncthreads();

        unsigned long long v2[6][3];
#pragma unroll
        for (int r = 0; r < 6; r++)
#pragma unroll
            for (int d = 0; d < 3; d++) {
                float v = patch[(ty * 4 + r) * 34 + tx + d];
                v2[r][d] = pack2(v, v);
            }

#pragma unroll
        for (int pr = 0; pr < PAIRS; pr++) {
            unsigned long long w2[9];
#pragma unroll
            for (int j = 0; j < 9; j++) w2[j] = wsm[pr * 9 + j];
#pragma unroll
            for (int p = 0; p < 4; p++) {
#pragma unroll
                for (int dy = 0; dy < 3; dy++)
#pragma unroll
                    for (int dx = 0; dx < 3; dx++)
                        ffma2(acc[pr][p], w2[dy * 3 + dx], v2[p + dy][dx]);
            }
        }
    }

#pragma unroll
    for (int pr = 0; pr < PAIRS; pr++) {
        int c0 = co0 + 2 * pr;
        float b0 = bias[c0], b1 = bias[c0 + 1];
#pragma unroll
        for (int p = 0; p < 4; p++) {
            float r0, r1;
            unpack2(acc[pr][p], r0, r1);
            r0 += b0; r1 += b1;
            int oy = oy0 + p;
            if (addend) {
                r0 += addend[(((long long)b * addCtot + addCoff + c0)     * H + oy) * W + ox];
                r1 += addend[(((long long)b * addCtot + addCoff + c0 + 1) * H + oy) * W + ox];
            }
            if (doLrelu) {
                r0 = r0 > 0.f ? r0 : 0.2f * r0;
                r1 = r1 > 0.f ? r1 : 0.2f * r1;
            }
            out[(((long long)b * outCtot + outCoff + c0)     * H + oy) * W + ox] = r0;
            out[(((long long)b * outCtot + outCoff + c0 + 1) * H + oy) * W + ox] = r1;
        }
    }
}

// ---------------------------------------------------------------------------
// tf32 tensor-core implicit-GEMM 3x3 conv (pad 1).
// Block: 256 threads = 8 warps (2 M-warps x 4 N-warps).
// Block tile: 64 output channels x 256 pixels (16x16 spatial).
// K-loop: 8 input channels per chunk; per chunk iterate 9 taps, each tap is
// one K=8 MMA step against a shifted view of the SMEM halo patch.
// Requires: Cout % 64 == 0, Cin % 8 == 0, H % 16 == 0, W % 16 == 0.
// ---------------------------------------------------------------------------
__global__ __launch_bounds__(256, 2)
void conv3x3_mma_k(const float* __restrict__ in, int Cin, int inCtot, int inCoff,
                   const float* __restrict__ wgt, const float* __restrict__ bias,
                   float* __restrict__ out, int outCtot, int outCoff,
                   int H, int W,
                   const float* __restrict__ addend, int addCtot, int addCoff,
                   int doLrelu) {
    __shared__ unsigned patch[8][18][20];   // [ci][y][x], halo'd, conflict-free
    __shared__ unsigned wsm[9][64][9];      // [tap][co][ci] (ci padded 8->9)

    const int tid  = threadIdx.x;
    const int lane = tid & 31;
    const int warp = tid >> 5;
    const int gid  = lane >> 2;   // 0..7
    const int tig  = lane & 3;    // 0..3
    const int mwarp = warp & 1;   // 0..1 -> 32 channels each
    const int nwarp = warp >> 1;  // 0..3 -> 64 pixels each

    const int tilesX = W >> 4;
    const int tx0 = (blockIdx.x % tilesX) << 4;
    const int ty0 = (blockIdx.x / tilesX) << 4;
    const int co0 = blockIdx.y << 6;
    const int b   = blockIdx.z;

    float acc[2][8][4];
#pragma unroll
    for (int mt = 0; mt < 2; mt++)
#pragma unroll
        for (int nt = 0; nt < 8; nt++)
#pragma unroll
            for (int r = 0; r < 4; r++) acc[mt][nt][r] = 0.f;

    const long long inBase = ((long long)b * inCtot + inCoff) * H * W;

    for (int ci0 = 0; ci0 < Cin; ci0 += 8) {
        __syncthreads();
        // stage input patch: 8 channels x 18x18 halo
        for (int idx = tid; idx < 8 * 18 * 18; idx += 256) {
            int ci = idx / 324;
            int rem = idx - ci * 324;
            int r = rem / 18, c = rem - r * 18;
            int gy = ty0 - 1 + r, gx = tx0 - 1 + c;
            float v = 0.f;
            if ((unsigned)gy < (unsigned)H && (unsigned)gx < (unsigned)W)
                v = in[inBase + (long long)(ci0 + ci) * H * W + gy * W + gx];
            patch[ci][r][c] = tf32b(v);
        }
        // stage weights: 64co x 8ci x 9 taps
        for (int idx = tid; idx < 64 * 8 * 9; idx += 256) {
            int co = idx / 72;
            int rem = idx - co * 72;
            int ci = rem / 9, j = rem - ci * 9;
            float v = wgt[((long long)(co0 + co) * Cin + ci0 + ci) * 9 + j];
            wsm[j][co][ci] = tf32b(v);
        }
        __syncthreads();

#pragma unroll
        for (int j = 0; j < 9; j++) {
            const int dy = j / 3, dx = j % 3;
            unsigned a[2][4];
#pragma unroll
            for (int mt = 0; mt < 2; mt++) {
                int cl = mwarp * 32 + mt * 16;
                a[mt][0] = wsm[j][cl + gid][tig];
                a[mt][1] = wsm[j][cl + gid + 8][tig];
                a[mt][2] = wsm[j][cl + gid][tig + 4];
                a[mt][3] = wsm[j][cl + gid + 8][tig + 4];
            }
#pragma unroll
            for (int nt = 0; nt < 8; nt++) {
                int pix = nwarp * 64 + nt * 8;
                int py = pix >> 4, px0 = pix & 15;
                unsigned b0 = patch[tig][py + dy][px0 + gid + dx];
                unsigned b1 = patch[tig + 4][py + dy][px0 + gid + dx];
                mma8(acc[0][nt], a[0], b0, b1);
                mma8(acc[1][nt], a[1], b0, b1);
            }
        }
    }

    // epilogue: bias (+addend) (+lrelu), float2 stores
#pragma unroll
    for (int mt = 0; mt < 2; mt++) {
#pragma unroll
        for (int rr = 0; rr < 2; rr++) {
            int co = co0 + mwarp * 32 + mt * 16 + rr * 8 + gid;
            float bv = bias[co];
            long long obase = ((long long)b * outCtot + outCoff + co) * H;
            long long abase = addend ? ((long long)b * addCtot + addCoff + co) * H : 0;
#pragma unroll
            for (int nt = 0; nt < 8; nt++) {
                int pix = nwarp * 64 + nt * 8;
                int oy = ty0 + (pix >> 4);
                int ox = tx0 + (pix & 15) + 2 * tig;
                float v0 = acc[mt][nt][rr * 2]     + bv;
                float v1 = acc[mt][nt][rr * 2 + 1] + bv;
                if (addend) {
                    const float* ap = addend + (abase + oy) * W + ox;
                    v0 += ap[0];
                    v1 += ap[1];
                }
                if (doLrelu) {
                    v0 = v0 > 0.f ? v0 : 0.2f * v0;
                    v1 = v1 > 0.f ? v1 : 0.2f * v1;
                }
                float2 val = make_float2(v0, v1);
                *reinterpret_cast<float2*>(out + (obase + oy) * W + ox) = val;
            }
        }
    }
}

// ---------------------------------------------------------------------------
// Orchestration
// ---------------------------------------------------------------------------
static inline void launch_conv_small(const float* in, int Cin, int inCtot, int inCoff,
                                     const float* w, const float* bvec,
                                     float* out, int Cout, int outCtot, int outCoff,
                                     int H, int W, int doLrelu) {
    dim3 bdim(32, 8);
    if (Cout >= 8) {
        int numCog = Cout / 8;
        dim3 grid(W / 32, H / 32, 8 * numCog);
        conv3x3_k<4><<<grid, bdim>>>(in, Cin, inCtot, inCoff, w, bvec,
                                     out, outCtot, outCoff, H, W, numCog,
                                     nullptr, 0, 0, doLrelu);
    } else {
        int numCog = Cout / 4;
        dim3 grid(W / 32, H / 32, 8 * numCog);
        conv3x3_k<2><<<grid, bdim>>>(in, Cin, inCtot, inCoff, w, bvec,
                                     out, outCtot, outCoff, H, W, numCog,
                                     nullptr, 0, 0, doLrelu);
    }
}

static inline void launch_conv_mma(const float* in, int Cin, int inCtot, int inCoff,
                                   const float* w, const float* bvec,
                                   float* out, int Cout, int outCtot, int outCoff,
                                   int H, int W,
                                   const float* addend, int addCtot, int addCoff,
                                   int doLrelu) {
    dim3 grid((W / 16) * (H / 16), Cout / 64, 8);
    conv3x3_mma_k<<<grid, 256>>>(in, Cin, inCtot, inCoff, w, bvec,
                                 out, outCtot, outCoff, H, W,
                                 addend, addCtot, addCoff, doLrelu);
}

extern "C" void kernel_launch(void* const* d_in, const int* in_sizes, int n_in,
                              void* d_out, int out_size) {
    const float* x        = (const float*)d_in[0];
    const float* conv1_w  = (const float*)d_in[1];
    const float* conv1_b  = (const float*)d_in[2];
    const float* conv2_w  = (const float*)d_in[3];
    const float* conv2_b  = (const float*)d_in[4];
    const float* conv3_w  = (const float*)d_in[5];
    const float* conv3_b  = (const float*)d_in[6];
    const float* conv4_w  = (const float*)d_in[7];
    const float* conv4_b  = (const float*)d_in[8];
    const float* convd1_w = (const float*)d_in[9];
    const float* convd1_b = (const float*)d_in[10];
    const float* convd2_w = (const float*)d_in[11];
    const float* convd2_b = (const float*)d_in[12];
    const float* convd3_w = (const float*)d_in[13];
    const float* convd3_b = (const float*)d_in[14];
    const float* convd4_w = (const float*)d_in[15];
    const float* convd4_b = (const float*)d_in[16];
    float* out = (float*)d_out;

    float *w1, *cat2, *w2, *cat3, *w3, *cat4, *w4, *c4, *c5, *ic4, *ic3, *ic2, *ic1, *iw1;
    cudaGetSymbolAddress((void**)&w1,  g_w1);
    cudaGetSymbolAddress((void**)&cat2, g_cat2);
    cudaGetSymbolAddress((void**)&w2,  g_w2);
    cudaGetSymbolAddress((void**)&cat3, g_cat3);
    cudaGetSymbolAddress((void**)&w3,  g_w3);
    cudaGetSymbolAddress((void**)&cat4, g_cat4);
    cudaGetSymbolAddress((void**)&w4,  g_w4);
    cudaGetSymbolAddress((void**)&c4,  g_c4);
    cudaGetSymbolAddress((void**)&c5,  g_c5);
    cudaGetSymbolAddress((void**)&ic4, g_ic4);
    cudaGetSymbolAddress((void**)&ic3, g_ic3);
    cudaGetSymbolAddress((void**)&ic2, g_ic2);
    cudaGetSymbolAddress((void**)&ic1, g_ic1);
    cudaGetSymbolAddress((void**)&iw1, g_iw1);

    const int B = 8;
    int tot;

    // --- encoder ---
    tot = B * 1 * 256 * 256;
    wt_k<<<(tot + 255) / 256, 256>>>(x, 1, 0, w1, 1, 256, 256, tot);

    // c1 = lrelu(conv1(w1)) -> cat2[ch 0..15]   (4->16 @256², scalar)
    launch_conv_small(w1, 4, 4, 0, conv1_w, conv1_b, cat2, 16, 32, 0, 256, 256, 1);

    tot = B * 16 * 128 * 128;
    wt_k<<<(tot + 255) / 256, 256>>>(cat2, 32, 0, w2, 16, 128, 128, tot);

    // c2 = lrelu(conv2(w2)) -> cat3[ch 0..63]   (64->64 @128², mma)
    launch_conv_mma(w2, 64, 64, 0, conv2_w, conv2_b, cat3, 64, 128, 0, 128, 128,
                    nullptr, 0, 0, 1);

    tot = B * 64 * 64 * 64;
    wt_k<<<(tot + 255) / 256, 256>>>(cat3, 128, 0, w3, 64, 64, 64, tot);

    // c3 = lrelu(conv3(w3)) -> cat4[ch 0..255]  (256->256 @64², mma)
    launch_conv_mma(w3, 256, 256, 0, conv3_w, conv3_b, cat4, 256, 512, 0, 64, 64,
                    nullptr, 0, 0, 1);

    tot = B * 256 * 32 * 32;
    wt_k<<<(tot + 255) / 256, 256>>>(cat4, 512, 0, w4, 256, 32, 32, tot);

    // --- bottleneck: conv4 x3 (1024->1024 @32², mma) ---
    launch_conv_mma(w4, 1024, 1024, 0, conv4_w, conv4_b, c4, 1024, 1024, 0, 32, 32,
                    nullptr, 0, 0, 1);
    launch_conv_mma(c4, 1024, 1024, 0, conv4_w, conv4_b, c5, 1024, 1024, 0, 32, 32,
                    nullptr, 0, 0, 1);
    launch_conv_mma(c5, 1024, 1024, 0, conv4_w, conv4_b, ic4, 1024, 1024, 0, 32, 32,
                    w4, 1024, 0, 1);   // + w4 residual, lrelu

    // --- decoder ---
    tot = B * 256 * 32 * 32;
    iwt_k<<<(tot + 255) / 256, 256>>>(ic4, 256, 32, 32, cat4, 512, 256, 0, tot);

    // ic3 = lrelu(convd4(cat4))  (512->256 @64², mma)
    launch_conv_mma(cat4, 512, 512, 0, convd4_w, convd4_b, ic3, 256, 256, 0, 64, 64,
                    nullptr, 0, 0, 1);

    tot = B * 64 * 64 * 64;
    iwt_k<<<(tot + 255) / 256, 256>>>(ic3, 64, 64, 64, cat3, 128, 64, 0, tot);

    // ic2 = lrelu(convd3(cat3))  (128->64 @128², mma)
    launch_conv_mma(cat3, 128, 128, 0, convd3_w, convd3_b, ic2, 64, 64, 0, 128, 128,
                    nullptr, 0, 0, 1);

    tot = B * 16 * 128 * 128;
    iwt_k<<<(tot + 255) / 256, 256>>>(ic2, 16, 128, 128, cat2, 32, 16, 0, tot);

    // ic1 = lrelu(convd2(cat2))  (32->16 @256², scalar)
    launch_conv_small(cat2, 32, 32, 0, convd2_w, convd2_b, ic1, 16, 16, 0, 256, 256, 1);

    // iw1 = lrelu(convd1(ic1))   (16->4 @256², scalar)
    launch_conv_small(ic1, 16, 16, 0, convd1_w, convd1_b, iw1, 4, 4, 0, 256, 256, 1);

    tot = B * 1 * 256 * 256;
    iwt_k<<<(tot + 255) / 256, 256>>>(iw1, 1, 256, 256, out, 1, 0, 1, tot);

    (void)in_sizes; (void)n_in; (void)out_size;
}